// round 8
// baseline (speedup 1.0000x reference)
#include <cuda_runtime.h>
#include <cuda_fp16.h>
#include <cstdint>

// ---------------- problem constants ----------------
#define T_STEPS 256
#define HID     256
#define EMBD    10
#define NCLS    10

// ---------------- geometry -------------------------
#define CLUSTER  8
#define GRID_X   128            // 16 clusters x 8 CTAs
#define NTHREADS 512            // 16 warps
#define MROWS    64             // batch rows per cluster
// per-CTA GEMM: M=64, N=128 (permuted j'), K=272 (256 h + 10 x + 2 bias)
// warp grid: 2 (M) x 8 (N) -> warp tile M32 x N16

// ---------------- smem layout (bytes) --------------
#define KPAD  280               // halfs per row (bank-conflict-free LDSM stride)
#define STRB  (KPAD * 2)        // 560 B row stride
#define OFF_WHI 0
#define W_SZ   (128 * STRB)     // 71,680
#define OFF_WLO (OFF_WHI + W_SZ)
#define OFF_AHI (OFF_WLO + W_SZ)      // 143,360
#define A_SZ   (64 * STRB)            // 35,840
#define OFF_ALO (OFF_AHI + A_SZ)
#define SMEM_BYTES (OFF_ALO + A_SZ)   // 215,040

// ---------------- helpers --------------------------
__device__ __forceinline__ uint32_t smem_u32(const void* p) {
    uint32_t a;
    asm("{ .reg .u64 t; cvta.to.shared.u64 t, %1; cvt.u32.u64 %0, t; }" : "=r"(a) : "l"(p));
    return a;
}
__device__ __forceinline__ uint32_t ctarank() {
    uint32_t r; asm("mov.u32 %0, %%cluster_ctarank;" : "=r"(r)); return r;
}
__device__ __forceinline__ uint32_t mapa_u32(uint32_t a, uint32_t r) {
    uint32_t d; asm("mapa.shared::cluster.u32 %0, %1, %2;" : "=r"(d) : "r"(a), "r"(r));
    return d;
}
__device__ __forceinline__ void cluster_arrive_() {
    asm volatile("barrier.cluster.arrive.aligned;" ::: "memory");
}
__device__ __forceinline__ void cluster_wait_() {
    asm volatile("barrier.cluster.wait.aligned;" ::: "memory");
}

#define LDSM4(R, ADDR)                                                          \
    asm volatile("ldmatrix.sync.aligned.m8n8.x4.shared.b16 {%0,%1,%2,%3},[%4];" \
                 : "=r"((R)[0]), "=r"((R)[1]), "=r"((R)[2]), "=r"((R)[3])       \
                 : "r"(ADDR))

#define MMA(D, A, B0, B1)                                                       \
    asm volatile("mma.sync.aligned.m16n8k16.row.col.f32.f16.f16.f32 "           \
                 "{%0,%1,%2,%3},{%4,%5,%6,%7},{%8,%9},{%0,%1,%2,%3};"           \
                 : "+f"((D)[0]), "+f"((D)[1]), "+f"((D)[2]), "+f"((D)[3])       \
                 : "r"((A)[0]), "r"((A)[1]), "r"((A)[2]), "r"((A)[3]),          \
                   "r"(B0), "r"(B1))

__device__ __forceinline__ float sigm(float x) {
    float e, r;
    asm("ex2.approx.f32 %0,%1;" : "=f"(e) : "f"(-x * 1.4426950408889634f));
    asm("rcp.approx.f32 %0,%1;" : "=f"(r) : "f"(1.0f + e));
    return r;
}
__device__ __forceinline__ float tanh_(float x) { return fmaf(2.0f, sigm(2.0f * x), -1.0f); }

__device__ __forceinline__ void sts_h16(uint32_t addr, __half v) {
    asm volatile("st.shared.b16 [%0], %1;" :: "r"(addr), "h"(__half_as_ushort(v)) : "memory");
}
__device__ __forceinline__ void split16(float v, __half& hi, __half& lo) {
    hi = __float2half_rn(v);
    lo = __float2half_rn(v - __half2float(hi));
}

// column permutation: all 4 gates of one kk inside one n8 tile, lane-pair local
__device__ __forceinline__ int jprime(int kk, int g) {
    return ((kk >> 3) << 5) + ((kk & 3) << 3) + (((kk >> 2) & 1) << 2) + g;
}

// stage x-embedding for step t into A rows k=256..265 (hi & lo)
__device__ __forceinline__ void stage_x(const int* __restrict__ x,
                                        const float* __restrict__ emb,
                                        int clusterRow, int t, int tid, uint32_t sb) {
    if (tid < 128) {
        int m = tid >> 1, half = tid & 1;
        int tok = __ldg(&x[(clusterRow + m) * T_STEPS + t]);
        const float* er = emb + (long)tok * EMBD + half * 5;
        uint32_t ab = sb + OFF_AHI + (uint32_t)m * STRB;
        #pragma unroll
        for (int e = 0; e < 5; ++e) {
            float v = __ldg(er + e);
            __half hi, lo; split16(v, hi, lo);
            uint32_t o = (uint32_t)((256 + half * 5 + e) * 2);
            sts_h16(ab + o, hi);
            sts_h16(ab + A_SZ + o, lo);
        }
    }
}

__global__ __launch_bounds__(NTHREADS, 1) __cluster_dims__(CLUSTER, 1, 1)
void lstm_hmma_kernel(const int*   __restrict__ x,   const float* __restrict__ emb,
                      const float* __restrict__ Wgx, const float* __restrict__ Wgh, const float* __restrict__ bg,
                      const float* __restrict__ Wix, const float* __restrict__ Wih, const float* __restrict__ bi,
                      const float* __restrict__ Wfx, const float* __restrict__ Wfh, const float* __restrict__ bf,
                      const float* __restrict__ Wox, const float* __restrict__ Woh, const float* __restrict__ bo,
                      const float* __restrict__ Wph, const float* __restrict__ bp,
                      float* __restrict__ out)
{
    extern __shared__ char smem[];
    const int      tid  = threadIdx.x;
    const int      lane = tid & 31;
    const int      w    = tid >> 5;
    const uint32_t rank = ctarank();                  // 0..7
    const int clusterRow = (blockIdx.x >> 3) * MROWS; // cluster id * 64
    const uint32_t sb = smem_u32(smem);

    // ---------- zero W+A regions ----------
    for (int i = tid; i < SMEM_BYTES / 4; i += NTHREADS)
        *(uint32_t*)(smem + i * 4) = 0u;
    __syncthreads();

    // ---------- stage W (hi/lo) with permuted j', bias as K-rows 266/267 ----------
    {
        const float* Wh4[4] = {Wgh, Wih, Wfh, Woh};
        const float* Wx4[4] = {Wgx, Wix, Wfx, Wox};
        const float* b4[4]  = {bg, bi, bf, bo};
        #pragma unroll
        for (int g = 0; g < 4; ++g) {
            for (int idx = tid; idx < 32 * HID; idx += NTHREADS) {
                int kk = idx & 31, k = idx >> 5;
                int j = jprime(kk, g);
                float v = Wh4[g][k * HID + (int)rank * 32 + kk];
                __half hi, lo; split16(v, hi, lo);
                uint32_t o = (uint32_t)j * STRB + (uint32_t)(k * 2);
                sts_h16(sb + OFF_WHI + o, hi);
                sts_h16(sb + OFF_WLO + o, lo);
            }
            for (int idx = tid; idx < 32 * EMBD; idx += NTHREADS) {
                int kk = idx & 31, e = idx >> 5;
                int j = jprime(kk, g);
                float v = Wx4[g][e * HID + (int)rank * 32 + kk];
                __half hi, lo; split16(v, hi, lo);
                uint32_t o = (uint32_t)j * STRB + (uint32_t)((256 + e) * 2);
                sts_h16(sb + OFF_WHI + o, hi);
                sts_h16(sb + OFF_WLO + o, lo);
            }
            if (tid < 32) {
                int j = jprime(tid, g);
                float v = b4[g][(int)rank * 32 + tid];
                __half hi, lo; split16(v, hi, lo);
                sts_h16(sb + OFF_WHI + (uint32_t)j * STRB + 266u * 2, hi);
                sts_h16(sb + OFF_WHI + (uint32_t)j * STRB + 267u * 2, lo);
            }
        }
    }
    // A constant-1 rows for bias (hi region only)
    for (int m = tid; m < MROWS; m += NTHREADS) {
        uint32_t ab = sb + OFF_AHI + (uint32_t)m * STRB;
        sts_h16(ab + 266u * 2, __float2half_rn(1.0f));
        sts_h16(ab + 267u * 2, __float2half_rn(1.0f));
    }
    stage_x(x, emb, clusterRow, 0, tid, sb);   // x for t=0 (h part zero)
    __syncthreads();

    // ---------- GEMM thread mapping: 16 warps = 2(M) x 8(N) ----------
    const int mg = w & 1;          // m slab: rows mg*32..+31
    const int ng = w >> 1;         // n slab: j' ng*16..+15
    const uint32_t laneOff = (uint32_t)(((((lane >> 3) & 1) * 8 + (lane & 7)) * STRB) + ((lane >> 4) * 16));
    const uint32_t aHiB = sb + OFF_AHI + (uint32_t)(mg * 32) * STRB + laneOff;
    const uint32_t aLoB = aHiB + A_SZ;
    const uint32_t bHiB = sb + OFF_WHI + (uint32_t)(ng * 16) * STRB + laneOff;
    const uint32_t bLoB = bHiB + W_SZ;

    const int dm    = lane >> 2;
    const int codd  = lane & 1;          // 0: row dm, gates (g,i) ; 1: row dm+8, gates (f,o)
    const int chigh = (lane >> 1) & 1;   // (kk>>2)&1

    // DSMEM peer bases for A_hi (stagger start by rank)
    uint32_t peerA[CLUSTER];
    #pragma unroll
    for (int p = 0; p < CLUSTER; ++p)
        peerA[p] = mapa_u32(sb + OFF_AHI, (uint32_t)((p + rank) & 7));

    // this thread's cells: rows mrow0 + mt*16 ; kk = kk0 + nt (nt = 0,1)
    const int mrow0 = mg * 32 + dm + (codd ? 8 : 0);
    const int o8    = ng >> 1;
    const int kk0   = o8 * 8 + chigh * 4 + (ng & 1) * 2;   // local kk, +nt
    const int gk0   = (int)rank * 32 + kk0;                // global k index in A row

    float c8[4];
    #pragma unroll
    for (int i = 0; i < 4; ++i) c8[i] = 0.0f;

    for (int t = 0; t < T_STEPS; ++t) {
        // ---------------- software-pipelined GEMM ----------------
        float d[2][2][4];
        #pragma unroll
        for (int a = 0; a < 2; ++a)
            #pragma unroll
            for (int b = 0; b < 2; ++b)
                #pragma unroll
                for (int c = 0; c < 4; ++c) d[a][b][c] = 0.0f;

        // fragment stages: [ah0 ah1 al0 al1 bh bl] = 24 regs each
        uint32_t f[2][24];

        #define LDFRAG(s, kc) do {                                   \
            const uint32_t ka = (uint32_t)(kc) * 32;                 \
            LDSM4(&f[s][0],  aHiB + ka);                             \
            LDSM4(&f[s][4],  aHiB + ka + 16 * STRB);                 \
            LDSM4(&f[s][8],  aLoB + ka);                             \
            LDSM4(&f[s][12], aLoB + ka + 16 * STRB);                 \
            LDSM4(&f[s][16], bHiB + ka);                             \
            LDSM4(&f[s][20], bLoB + ka);                             \
        } while (0)

        #define COMP(s) do {                                         \
            _Pragma("unroll")                                        \
            for (int mt = 0; mt < 2; ++mt) {                         \
                uint32_t* ah = &f[s][mt * 4];                        \
                uint32_t* al = &f[s][8 + mt * 4];                    \
                uint32_t* bh = &f[s][16];                            \
                uint32_t* bl = &f[s][20];                            \
                _Pragma("unroll")                                    \
                for (int nt = 0; nt < 2; ++nt) {                     \
                    MMA(d[mt][nt], ah, bh[nt], bh[nt + 2]);          \
                    MMA(d[mt][nt], ah, bl[nt], bl[nt + 2]);          \
                    MMA(d[mt][nt], al, bh[nt], bh[nt + 2]);          \
                }                                                    \
            }                                                        \
        } while (0)

        LDFRAG(0, 0);
        #pragma unroll
        for (int kc = 0; kc < 17; ++kc) {
            if (kc < 16) LDFRAG((kc + 1) & 1, kc + 1);
            COMP(kc & 1);
        }
        #undef LDFRAG
        #undef COMP

        cluster_arrive_();   // done reading A; epilogue is register-only

        // ---------------- register epilogue (shfl gate exchange) ----------------
        uint32_t hp[2], lp[2];   // packed h (hi/lo) per mt: halfs (kk0, kk0+1)
        #pragma unroll
        for (int mt = 0; mt < 2; ++mt) {
            __half hh[2], hl[2];
            #pragma unroll
            for (int nt = 0; nt < 2; ++nt) {
                float d0 = d[mt][nt][0], d1 = d[mt][nt][1];
                float d2 = d[mt][nt][2], d3 = d[mt][nt][3];
                float pd0 = __shfl_xor_sync(0xffffffffu, d0, 1);
                float pd1 = __shfl_xor_sync(0xffffffffu, d1, 1);
                float pd2 = __shfl_xor_sync(0xffffffffu, d2, 1);
                float pd3 = __shfl_xor_sync(0xffffffffu, d3, 1);
                float zg, zi, zf, zo;
                if (!codd) { zg = d0;  zi = d1;  zf = pd0; zo = pd1; }
                else       { zg = pd2; zi = pd3; zf = d2;  zo = d3;  }
                float gg = tanh_(zg);
                float ii = sigm(zi);
                float ff = sigm(zf);
                float oo = sigm(zo);
                float cn = fmaf(gg, ii, c8[mt * 2 + nt] * ff);
                c8[mt * 2 + nt] = cn;
                float hn = tanh_(cn) * oo;
                split16(hn, hh[nt], hl[nt]);
            }
            hp[mt] = (uint32_t)__half_as_ushort(hh[0]) | ((uint32_t)__half_as_ushort(hh[1]) << 16);
            lp[mt] = (uint32_t)__half_as_ushort(hl[0]) | ((uint32_t)__half_as_ushort(hl[1]) << 16);
        }

        cluster_wait_();     // all CTAs done reading A -> safe to overwrite

        // ---------------- DSMEM push: h -> all 8 cluster A replicas ----------------
        #pragma unroll
        for (int mt = 0; mt < 2; ++mt) {
            uint32_t off = (uint32_t)(mrow0 + mt * 16) * STRB + (uint32_t)(gk0 * 2);
            #pragma unroll
            for (int p = 0; p < CLUSTER; ++p) {
                asm volatile("st.shared::cluster.b32 [%0],%1;"
                             :: "r"(peerA[p] + off), "r"(hp[mt]) : "memory");
                asm volatile("st.shared::cluster.b32 [%0],%1;"
                             :: "r"(peerA[p] + off + A_SZ), "r"(lp[mt]) : "memory");
            }
        }
        if (t != T_STEPS - 1)
            stage_x(x, emb, clusterRow, t + 1, tid, sb);

        cluster_arrive_();   // pushes ordered-before arrive (release)
        cluster_wait_();     // all pushes visible -> next GEMM may read
    }

    // ---------------- final projection: out = h(255) @ Wph + bp ----------------
    if (tid < 8 * NCLS) {
        int mi = tid / NCLS, cl = tid - mi * NCLS;
        int m  = (int)rank * 8 + mi;
        float s = __ldg(&bp[cl]);
        #pragma unroll 4
        for (int k = 0; k < HID; ++k) {
            __half hi = *(const __half*)(smem + OFF_AHI + m * STRB + k * 2);
            __half lo = *(const __half*)(smem + OFF_ALO + m * STRB + k * 2);
            float hv = __half2float(hi) + __half2float(lo);
            s = fmaf(hv, __ldg(&Wph[k * NCLS + cl]), s);
        }
        out[(clusterRow + m) * NCLS + cl] = s;
    }
}

// ---------------- host launch ----------------------
extern "C" void kernel_launch(void* const* d_in, const int* in_sizes, int n_in,
                              void* d_out, int out_size)
{
    const int*   x   = (const int*)  d_in[0];
    const float* emb = (const float*)d_in[1];
    const float* Wgx = (const float*)d_in[2];
    const float* Wgh = (const float*)d_in[3];
    const float* bg  = (const float*)d_in[4];
    const float* Wix = (const float*)d_in[5];
    const float* Wih = (const float*)d_in[6];
    const float* bi  = (const float*)d_in[7];
    const float* Wfx = (const float*)d_in[8];
    const float* Wfh = (const float*)d_in[9];
    const float* bf  = (const float*)d_in[10];
    const float* Wox = (const float*)d_in[11];
    const float* Woh = (const float*)d_in[12];
    const float* bo  = (const float*)d_in[13];
    const float* Wph = (const float*)d_in[14];
    const float* bp  = (const float*)d_in[15];

    cudaFuncSetAttribute(lstm_hmma_kernel,
                         cudaFuncAttributeMaxDynamicSharedMemorySize, SMEM_BYTES);

    lstm_hmma_kernel<<<GRID_X, NTHREADS, SMEM_BYTES>>>(
        x, emb, Wgx, Wgh, bg, Wix, Wih, bi, Wfx, Wfh, bf, Wox, Woh, bo,
        Wph, bp, (float*)d_out);
}

// round 9
// speedup vs baseline: 1.4350x; 1.4350x over previous
#include <cuda_runtime.h>
#include <cuda_fp16.h>
#include <cstdint>

// ---------------- problem constants ----------------
#define T_STEPS 256
#define HID     256
#define EMBD    10
#define NCLS    10

// ---------------- geometry -------------------------
#define CLUSTER  8
#define GRID_X   128            // 16 clusters x 8 CTAs
#define NTHREADS 256            // 8 warps: 2(M) x 4(N), warp tile M32 x N32
#define MROWS    64             // batch rows per cluster

// ---------------- smem layout (bytes) --------------
#define KPAD  280               // halfs per row; stride/16 = 35 (odd) -> LDSM conflict-free
#define STRB  (KPAD * 2)        // 560 B row stride
#define OFF_WHI 0
#define W_SZ   (128 * STRB)     // 71,680
#define OFF_WLO (OFF_WHI + W_SZ)
#define OFF_AHI (OFF_WLO + W_SZ)      // 143,360
#define A_SZ   (64 * STRB)            // 35,840
#define OFF_ALO (OFF_AHI + A_SZ)
#define OFF_STG (OFF_ALO + A_SZ)      // 215,040 : stage[2][64][32] packed u32
#define STG_BUF 8192
#define SMEM_BYTES (OFF_STG + 2 * STG_BUF)   // 231,424

// ---------------- helpers --------------------------
__device__ __forceinline__ uint32_t smem_u32(const void* p) {
    uint32_t a;
    asm("{ .reg .u64 t; cvta.to.shared.u64 t, %1; cvt.u32.u64 %0, t; }" : "=r"(a) : "l"(p));
    return a;
}
__device__ __forceinline__ uint32_t ctarank() {
    uint32_t r; asm("mov.u32 %0, %%cluster_ctarank;" : "=r"(r)); return r;
}
__device__ __forceinline__ uint32_t mapa_u32(uint32_t a, uint32_t r) {
    uint32_t d; asm("mapa.shared::cluster.u32 %0, %1, %2;" : "=r"(d) : "r"(a), "r"(r));
    return d;
}
__device__ __forceinline__ void cluster_arrive_() {
    asm volatile("barrier.cluster.arrive.aligned;" ::: "memory");
}
__device__ __forceinline__ void cluster_wait_() {
    asm volatile("barrier.cluster.wait.aligned;" ::: "memory");
}

#define LDSM4(R, ADDR)                                                          \
    asm volatile("ldmatrix.sync.aligned.m8n8.x4.shared.b16 {%0,%1,%2,%3},[%4];" \
                 : "=r"((R)[0]), "=r"((R)[1]), "=r"((R)[2]), "=r"((R)[3])       \
                 : "r"(ADDR))

#define MMA(D, A, B0, B1)                                                       \
    asm volatile("mma.sync.aligned.m16n8k16.row.col.f32.f16.f16.f32 "           \
                 "{%0,%1,%2,%3},{%4,%5,%6,%7},{%8,%9},{%0,%1,%2,%3};"           \
                 : "+f"((D)[0]), "+f"((D)[1]), "+f"((D)[2]), "+f"((D)[3])       \
                 : "r"((A)[0]), "r"((A)[1]), "r"((A)[2]), "r"((A)[3]),          \
                   "r"(B0), "r"(B1))

__device__ __forceinline__ float sigm(float x) {
    float e, r;
    asm("ex2.approx.f32 %0,%1;" : "=f"(e) : "f"(-x * 1.4426950408889634f));
    asm("rcp.approx.f32 %0,%1;" : "=f"(r) : "f"(1.0f + e));
    return r;
}
__device__ __forceinline__ float tanh_(float x) { return fmaf(2.0f, sigm(2.0f * x), -1.0f); }

__device__ __forceinline__ void sts_h16(uint32_t addr, __half v) {
    asm volatile("st.shared.b16 [%0], %1;" :: "r"(addr), "h"(__half_as_ushort(v)) : "memory");
}
__device__ __forceinline__ void split16(float v, __half& hi, __half& lo) {
    hi = __float2half_rn(v);
    lo = __float2half_rn(v - __half2float(hi));
}

// column permutation: all 4 gates of one kk inside one n8 tile, lane-pair local
__device__ __forceinline__ int jprime(int kk, int g) {
    return ((kk >> 3) << 5) + ((kk & 3) << 3) + (((kk >> 2) & 1) << 2) + g;
}

// direct (non-prefetched) x staging, used only for t=0 during init
__device__ __forceinline__ void stage_x0(const int* __restrict__ x,
                                         const float* __restrict__ emb,
                                         int clusterRow, int tid, uint32_t sb) {
    if (tid < 128) {
        int m = tid >> 1, half = tid & 1;
        int tok = __ldg(&x[(clusterRow + m) * T_STEPS + 0]);
        const float* er = emb + (long)tok * EMBD + half * 5;
        uint32_t ab = sb + OFF_AHI + (uint32_t)m * STRB;
        #pragma unroll
        for (int e = 0; e < 5; ++e) {
            float v = __ldg(er + e);
            __half hi, lo; split16(v, hi, lo);
            uint32_t o = (uint32_t)((256 + half * 5 + e) * 2);
            sts_h16(ab + o, hi);
            sts_h16(ab + A_SZ + o, lo);
        }
    }
}

__global__ __launch_bounds__(NTHREADS, 1) __cluster_dims__(CLUSTER, 1, 1)
void lstm_hmma_kernel(const int*   __restrict__ x,   const float* __restrict__ emb,
                      const float* __restrict__ Wgx, const float* __restrict__ Wgh, const float* __restrict__ bg,
                      const float* __restrict__ Wix, const float* __restrict__ Wih, const float* __restrict__ bi,
                      const float* __restrict__ Wfx, const float* __restrict__ Wfh, const float* __restrict__ bf,
                      const float* __restrict__ Wox, const float* __restrict__ Woh, const float* __restrict__ bo,
                      const float* __restrict__ Wph, const float* __restrict__ bp,
                      float* __restrict__ out)
{
    extern __shared__ char smem[];
    const int      tid  = threadIdx.x;
    const int      lane = tid & 31;
    const int      w    = tid >> 5;
    const uint32_t rank = ctarank();                  // 0..7
    const int clusterRow = (blockIdx.x >> 3) * MROWS; // cluster id * 64
    const uint32_t sb = smem_u32(smem);

    // ---------- zero everything ----------
    for (int i = tid; i < SMEM_BYTES / 4; i += NTHREADS)
        *(uint32_t*)(smem + i * 4) = 0u;
    __syncthreads();

    // ---------- stage W (hi/lo), permuted j'; bias as K-rows 266/267 ----------
    {
        const float* Wh4[4] = {Wgh, Wih, Wfh, Woh};
        const float* Wx4[4] = {Wgx, Wix, Wfx, Wox};
        const float* b4[4]  = {bg, bi, bf, bo};
        #pragma unroll
        for (int g = 0; g < 4; ++g) {
            for (int idx = tid; idx < 32 * HID; idx += NTHREADS) {
                int kk = idx & 31, k = idx >> 5;
                int j = jprime(kk, g);
                float v = Wh4[g][k * HID + (int)rank * 32 + kk];
                __half hi, lo; split16(v, hi, lo);
                uint32_t o = (uint32_t)j * STRB + (uint32_t)(k * 2);
                sts_h16(sb + OFF_WHI + o, hi);
                sts_h16(sb + OFF_WLO + o, lo);
            }
            for (int idx = tid; idx < 32 * EMBD; idx += NTHREADS) {
                int kk = idx & 31, e = idx >> 5;
                int j = jprime(kk, g);
                float v = Wx4[g][e * HID + (int)rank * 32 + kk];
                __half hi, lo; split16(v, hi, lo);
                uint32_t o = (uint32_t)j * STRB + (uint32_t)((256 + e) * 2);
                sts_h16(sb + OFF_WHI + o, hi);
                sts_h16(sb + OFF_WLO + o, lo);
            }
            if (tid < 32) {
                int j = jprime(tid, g);
                float v = b4[g][(int)rank * 32 + tid];
                __half hi, lo; split16(v, hi, lo);
                sts_h16(sb + OFF_WHI + (uint32_t)j * STRB + 266u * 2, hi);
                sts_h16(sb + OFF_WHI + (uint32_t)j * STRB + 267u * 2, lo);
            }
        }
    }
    // A constant-1 rows for bias (hi region only)
    for (int m = tid; m < MROWS; m += NTHREADS) {
        uint32_t ab = sb + OFF_AHI + (uint32_t)m * STRB;
        sts_h16(ab + 266u * 2, __float2half_rn(1.0f));
        sts_h16(ab + 267u * 2, __float2half_rn(1.0f));
    }
    stage_x0(x, emb, clusterRow, tid, sb);
    __syncthreads();

    // ---------- GEMM mapping: 8 warps = 2(M) x 4(N), warp tile M32 x N32 ----------
    const int mg = w & 1;
    const int ng = w >> 1;
    const uint32_t laneOff = (uint32_t)(((((lane >> 3) & 1) * 8 + (lane & 7)) * STRB) + ((lane >> 4) * 16));
    const uint32_t aHiB = sb + OFF_AHI + (uint32_t)(mg * 32) * STRB + laneOff;
    const uint32_t aLoB = aHiB + A_SZ;
    const uint32_t bHiB = sb + OFF_WHI + (uint32_t)(ng * 32) * STRB + laneOff;
    const uint32_t bLoB = bHiB + W_SZ;

    const int dm    = lane >> 2;
    const int codd  = lane & 1;          // 0: row dm, gates (g,i) ; 1: row dm+8, gates (f,o)
    const int chigh = (lane >> 1) & 1;

    // staggered peer order; pg = actual peer rank, peerStg = its stage base
    int      pg[CLUSTER];
    uint32_t peerStg[CLUSTER];
    #pragma unroll
    for (int p = 0; p < CLUSTER; ++p) {
        pg[p] = (p + (int)rank) & 7;
        peerStg[p] = mapa_u32(sb + OFF_STG, (uint32_t)pg[p]);
    }

    const int mrow0 = mg * 32 + dm + (codd ? 8 : 0);   // + mt*16
    const int kk0   = ng * 8 + chigh * 4;              // local kk base (+nt)

    float c8[8];
    #pragma unroll
    for (int i = 0; i < 8; ++i) c8[i] = 0.0f;

    for (int t = 0; t < T_STEPS; ++t) {
        const uint32_t bufo = (uint32_t)(t & 1) * STG_BUF;

        // ---- prefetch x-embedding for t+1 (L2 latency hidden by GEMM) ----
        float pe[5];
        if (tid < 128 && t + 1 < T_STEPS) {
            int m = tid >> 1, half = tid & 1;
            int tok = __ldg(&x[(clusterRow + m) * T_STEPS + t + 1]);
            const float* er = emb + (long)tok * EMBD + half * 5;
            #pragma unroll
            for (int e = 0; e < 5; ++e) pe[e] = __ldg(er + e);
        }

        // ---------------- software-pipelined GEMM ----------------
        float d[2][4][4];
        #pragma unroll
        for (int a = 0; a < 2; ++a)
            #pragma unroll
            for (int b = 0; b < 4; ++b)
                #pragma unroll
                for (int c = 0; c < 4; ++c) d[a][b][c] = 0.0f;

        uint32_t f[2][32];   // [ah0 ah1 al0 al1 bh0 bh1 bl0 bl1] x 4 regs

        #define LDFRAG(s, kc) do {                                   \
            const uint32_t ka = (uint32_t)(kc) * 32;                 \
            LDSM4(&f[s][0],  aHiB + ka);                             \
            LDSM4(&f[s][4],  aHiB + ka + 16 * STRB);                 \
            LDSM4(&f[s][8],  aLoB + ka);                             \
            LDSM4(&f[s][12], aLoB + ka + 16 * STRB);                 \
            LDSM4(&f[s][16], bHiB + ka);                             \
            LDSM4(&f[s][20], bHiB + ka + 16 * STRB);                 \
            LDSM4(&f[s][24], bLoB + ka);                             \
            LDSM4(&f[s][28], bLoB + ka + 16 * STRB);                 \
        } while (0)

        #define COMP(s) do {                                         \
            _Pragma("unroll")                                        \
            for (int mt = 0; mt < 2; ++mt) {                         \
                uint32_t* ah = &f[s][mt * 4];                        \
                uint32_t* al = &f[s][8 + mt * 4];                    \
                _Pragma("unroll")                                    \
                for (int nt = 0; nt < 4; ++nt) {                     \
                    uint32_t* bh = (nt < 2) ? &f[s][16] : &f[s][20]; \
                    uint32_t* bl = (nt < 2) ? &f[s][24] : &f[s][28]; \
                    const int sI = nt & 1;                           \
                    MMA(d[mt][nt], ah, bh[sI], bh[sI + 2]);          \
                    MMA(d[mt][nt], ah, bl[sI], bl[sI + 2]);          \
                    MMA(d[mt][nt], al, bh[sI], bh[sI + 2]);          \
                }                                                    \
            }                                                        \
        } while (0)

        LDFRAG(0, 0);
        #pragma unroll
        for (int kc = 0; kc < 17; ++kc) {
            if (kc < 16) LDFRAG((kc + 1) & 1, kc + 1);
            COMP(kc & 1);
        }
        #undef LDFRAG
        #undef COMP

        // ---------------- register epilogue -> local stage ----------------
        #pragma unroll
        for (int mt = 0; mt < 2; ++mt) {
            uint32_t wv[4];
            #pragma unroll
            for (int nt = 0; nt < 4; ++nt) {
                float d0 = d[mt][nt][0], d1 = d[mt][nt][1];
                float d2 = d[mt][nt][2], d3 = d[mt][nt][3];
                float pd0 = __shfl_xor_sync(0xffffffffu, d0, 1);
                float pd1 = __shfl_xor_sync(0xffffffffu, d1, 1);
                float pd2 = __shfl_xor_sync(0xffffffffu, d2, 1);
                float pd3 = __shfl_xor_sync(0xffffffffu, d3, 1);
                float zg, zi, zf, zo;
                if (!codd) { zg = d0;  zi = d1;  zf = pd0; zo = pd1; }
                else       { zg = pd2; zi = pd3; zf = d2;  zo = d3;  }
                float gg = tanh_(zg);
                float ii = sigm(zi);
                float ff = sigm(zf);
                float oo = sigm(zo);
                float cn = fmaf(gg, ii, c8[mt * 4 + nt] * ff);
                c8[mt * 4 + nt] = cn;
                float hn = tanh_(cn) * oo;
                __half hh, hl; split16(hn, hh, hl);
                wv[nt] = (uint32_t)__half_as_ushort(hh) | ((uint32_t)__half_as_ushort(hl) << 16);
            }
            uint32_t so = sb + OFF_STG + bufo
                        + (uint32_t)(mrow0 + mt * 16) * 128 + (uint32_t)(kk0 * 4);
            asm volatile("st.shared.v4.b32 [%0],{%1,%2,%3,%4};"
                         :: "r"(so), "r"(wv[0]), "r"(wv[1]), "r"(wv[2]), "r"(wv[3]) : "memory");
        }

        // single barrier phase: local stage stores released to cluster
        cluster_arrive_();
        cluster_wait_();

        // ---------------- pull all 8 slabs into private A ----------------
        #pragma unroll 4
        for (int j = 0; j < 16; ++j) {
            int i   = tid + j * NTHREADS;      // 0..4095
            int p   = i >> 9;                  // peer slot
            int c   = i & 511;
            int row = c >> 3;
            int c4  = (c & 7) << 2;            // kk base within slab
            uint32_t ra = peerStg[p] + bufo + (uint32_t)row * 128 + (uint32_t)(c4 * 4);
            uint32_t v0, v1, v2, v3;
            asm volatile("ld.shared::cluster.v4.b32 {%0,%1,%2,%3},[%4];"
                         : "=r"(v0), "=r"(v1), "=r"(v2), "=r"(v3) : "r"(ra));
            uint32_t hi01 = __byte_perm(v0, v1, 0x5410);
            uint32_t hi23 = __byte_perm(v2, v3, 0x5410);
            uint32_t lo01 = __byte_perm(v0, v1, 0x7632);
            uint32_t lo23 = __byte_perm(v2, v3, 0x7632);
            uint32_t da = sb + OFF_AHI + (uint32_t)row * STRB
                        + (uint32_t)((pg[p] * 32 + c4) * 2);
            asm volatile("st.shared.v2.b32 [%0],{%1,%2};"
                         :: "r"(da), "r"(hi01), "r"(hi23) : "memory");
            asm volatile("st.shared.v2.b32 [%0],{%1,%2};"
                         :: "r"(da + A_SZ), "r"(lo01), "r"(lo23) : "memory");
        }

        // ---- x-embedding for t+1 from prefetched regs ----
        if (tid < 128 && t + 1 < T_STEPS) {
            int m = tid >> 1, half = tid & 1;
            uint32_t ab = sb + OFF_AHI + (uint32_t)m * STRB;
            #pragma unroll
            for (int e = 0; e < 5; ++e) {
                __half hi, lo; split16(pe[e], hi, lo);
                uint32_t o = (uint32_t)((256 + half * 5 + e) * 2);
                sts_h16(ab + o, hi);
                sts_h16(ab + A_SZ + o, lo);
            }
        }
        __syncthreads();   // A fully assembled for next step
    }

    // ---------------- final projection: out = h(255) @ Wph + bp ----------------
    if (tid < 8 * NCLS) {
        int mi = tid / NCLS, cl = tid - mi * NCLS;
        int m  = (int)rank * 8 + mi;
        float s = __ldg(&bp[cl]);
        #pragma unroll 4
        for (int k = 0; k < HID; ++k) {
            __half hi = *(const __half*)(smem + OFF_AHI + m * STRB + k * 2);
            __half lo = *(const __half*)(smem + OFF_ALO + m * STRB + k * 2);
            float hv = __half2float(hi) + __half2float(lo);
            s = fmaf(hv, __ldg(&Wph[k * NCLS + cl]), s);
        }
        out[(clusterRow + m) * NCLS + cl] = s;
    }
}

// ---------------- host launch ----------------------
extern "C" void kernel_launch(void* const* d_in, const int* in_sizes, int n_in,
                              void* d_out, int out_size)
{
    const int*   x   = (const int*)  d_in[0];
    const float* emb = (const float*)d_in[1];
    const float* Wgx = (const float*)d_in[2];
    const float* Wgh = (const float*)d_in[3];
    const float* bg  = (const float*)d_in[4];
    const float* Wix = (const float*)d_in[5];
    const float* Wih = (const float*)d_in[6];
    const float* bi  = (const float*)d_in[7];
    const float* Wfx = (const float*)d_in[8];
    const float* Wfh = (const float*)d_in[9];
    const float* bf  = (const float*)d_in[10];
    const float* Wox = (const float*)d_in[11];
    const float* Woh = (const float*)d_in[12];
    const float* bo  = (const float*)d_in[13];
    const float* Wph = (const float*)d_in[14];
    const float* bp  = (const float*)d_in[15];

    cudaFuncSetAttribute(lstm_hmma_kernel,
                         cudaFuncAttributeMaxDynamicSharedMemorySize, SMEM_BYTES);

    lstm_hmma_kernel<<<GRID_X, NTHREADS, SMEM_BYTES>>>(
        x, emb, Wgx, Wgh, bg, Wix, Wih, bi, Wfx, Wfh, bf, Wox, Woh, bo,
        Wph, bp, (float*)d_out);
}